// round 15
// baseline (speedup 1.0000x reference)
#include <cuda_runtime.h>
#include <math.h>
#include <math_constants.h>

#define BB   2
#define TT   1024
#define DD   768
#define NHH  12
#define HS   512
#define HD   6144
#define LL   4
#define VOC  32000
#define ROWS (BB*TT)
#define KWTA_K 921   // int(6144*0.15)

// Eigen gebp panel depth (multithreaded heuristic: min((l1-ksub)/kdiv, 320) -> 320 cap)
#define KC 320

// ---------------- scratch (device globals: no allocation allowed) ----------------
__device__ float g_x[ROWS*DD];
__device__ float g_wenc[DD*HD];
__device__ float g_wencv[DD*HD];
__device__ float g_pre[ROWS*HD];
__device__ float g_pre2[ROWS*HD];
__device__ float g_qflat[ROWS*HD];
__device__ float g_qr[(long)BB*NHH*TT*HS];
__device__ float g_v [(long)BB*NHH*TT*HS];
__device__ float g_S [(long)BB*NHH*TT*TT];
__device__ float g_yt[(long)BB*NHH*TT*HS];
__device__ float g_y [ROWS*HD];
__device__ float g_dec[ROWS*DD];
__device__ float2 g_rope[TT*(HS/2)];

// f32 constant equal to fl32(2.0*math.pi)
#define TWO_PI_F ((float)6.2831853071795864769252867665590)
// f32 constant equal to fl32(math.sqrt(512.0))
#define SQRTN_F  ((float)22.6274169979695207808)

// ---------------- reductions ----------------
__device__ __forceinline__ float warpSum(float v){
    #pragma unroll
    for (int o=16;o;o>>=1) v += __shfl_xor_sync(0xffffffffu, v, o);
    return v;
}
__device__ __forceinline__ double warpSumD(double v){
    #pragma unroll
    for (int o=16;o;o>>=1) v += __shfl_xor_sync(0xffffffffu, v, o);
    return v;
}
__device__ __forceinline__ float warpMax(float v){
    #pragma unroll
    for (int o=16;o;o>>=1) v = fmaxf(v, __shfl_xor_sync(0xffffffffu, v, o));
    return v;
}
__device__ __forceinline__ float blockSum256(float v, float* sh){
    v = warpSum(v);
    if ((threadIdx.x & 31)==0) sh[threadIdx.x>>5] = v;
    __syncthreads();
    float r = (threadIdx.x < 8) ? sh[threadIdx.x] : 0.f;
    if ((threadIdx.x>>5)==0){ r = warpSum(r); if (threadIdx.x==0) sh[0]=r; }
    __syncthreads();
    r = sh[0];
    __syncthreads();
    return r;
}
__device__ __forceinline__ double blockSumD256(double v, double* sh){
    v = warpSumD(v);
    if ((threadIdx.x & 31)==0) sh[threadIdx.x>>5] = v;
    __syncthreads();
    double r = (threadIdx.x < 8) ? sh[threadIdx.x] : 0.0;
    if ((threadIdx.x>>5)==0){ r = warpSumD(r); if (threadIdx.x==0) sh[0]=r; }
    __syncthreads();
    r = sh[0];
    __syncthreads();
    return r;
}
__device__ __forceinline__ float blockMax256(float v, float* sh){
    v = warpMax(v);
    if ((threadIdx.x & 31)==0) sh[threadIdx.x>>5] = v;
    __syncthreads();
    float r = (threadIdx.x < 8) ? sh[threadIdx.x] : -CUDART_INF_F;
    if ((threadIdx.x>>5)==0){ r = warpMax(r); if (threadIdx.x==0) sh[0]=r; }
    __syncthreads();
    r = sh[0];
    __syncthreads();
    return r;
}

// ---------------- embed + input layernorm (two-pass, division semantics) --------
__global__ void embed_ln_kernel(const int* __restrict__ idx, const float* __restrict__ emb,
                                const float* __restrict__ w, const float* __restrict__ b,
                                float* __restrict__ x){
    __shared__ double shd[32];
    int r = blockIdx.x;
    const float* row = emb + (long)idx[r]*DD;
    float v[3]; double sum=0.0;
    #pragma unroll
    for (int i=0;i<3;i++){ v[i]=row[threadIdx.x + 256*i]; sum+=(double)v[i]; }
    sum = blockSumD256(sum, shd);
    float mu = __fdiv_rn((float)sum, (float)DD);
    double sq=0.0;
    #pragma unroll
    for (int i=0;i<3;i++){ float d=__fsub_rn(v[i],mu); sq+=(double)__fmul_rn(d,d); }
    sq = blockSumD256(sq, shd);
    float var = __fdiv_rn((float)sq, (float)DD);
    float sd  = sqrtf(__fadd_rn(var, 1e-5f));
    #pragma unroll
    for (int i=0;i<3;i++){
        int j=threadIdx.x+256*i;
        float n = __fdiv_rn(__fsub_rn(v[i],mu), sd);
        x[(long)r*DD+j] = __fadd_rn(__fmul_rn(n, w[j]), b[j]);
    }
}

// ---------------- repack encoder (NH,D,N) -> (D, NH*N) ----------------
__global__ void repack_enc_kernel(const float* __restrict__ enc, float* __restrict__ w){
    long i = (long)blockIdx.x*256 + threadIdx.x;   // over D*HD
    if (i >= (long)DD*HD) return;
    int n = (int)(i % HS); long r = i / HS;
    int h = (int)(r % NHH); int d = (int)(r / NHH);
    w[i] = enc[((long)h*DD + d)*HS + n];
}

// ---------------- rope table: correctly-rounded f32 chain (glibc/AOR proxy) -----
// glibc AOR powf/sinf/cosf are <=0.5-0.8 ulp (near-CR); computing in double and
// rounding reproduces them except on rare boundary cases.
__global__ void rope_table_kernel(float2* __restrict__ tab){
    int i = blockIdx.x*256 + threadIdx.x;           // t*(HS/2) + p
    if (i >= TT*(HS/2)) return;
    int p = i % (HS/2); int t = i / (HS/2);
    float e_f = __fdiv_rn((float)(2*p), 512.0f);    // exact (denominator 2^9)
    float pw  = (float)pow(10000.0, (double)e_f);   // CR f32 pow proxy
    float f1  = __fdiv_rn(1.0f, pw);
    float freq= __fdiv_rn(f1, TWO_PI_F);
    float ph  = __fmul_rn((float)t, freq);
    float frac= ph - floorf(ph);                    // exact for ph >= 0
    float ang = __fmul_rn(frac, TWO_PI_F);
    float c = (float)cos((double)ang);              // CR f32 cos proxy
    float s = (float)sin((double)ang);              // CR f32 sin proxy
    tab[i] = make_float2(c, s);
}

// ---------------- LN + relu + kWTA (two-pass LN, radix-select threshold) --------
template<bool TRANSV>
__global__ __launch_bounds__(256)
void ln_relu_kwta_kernel(const float* __restrict__ pre,
                         const float* __restrict__ w, const float* __restrict__ bia,
                         float* __restrict__ out){
    __shared__ double shd[32];
    __shared__ float shf[32];
    int r = blockIdx.x;                 // b*T + t
    const float* row = pre + (long)r*HD;
    float v[24];
    double sum = 0.0;
    #pragma unroll
    for (int i=0;i<24;i++){ v[i]=row[threadIdx.x + 256*i]; sum+=(double)v[i]; }
    sum = blockSumD256(sum, shd);
    float mu = __fdiv_rn((float)sum, (float)HD);
    double sq = 0.0;
    #pragma unroll
    for (int i=0;i<24;i++){ float d=__fsub_rn(v[i],mu); sq+=(double)__fmul_rn(d,d); }
    sq = blockSumD256(sq, shd);
    float var = __fdiv_rn((float)sq, (float)HD);
    float sd  = sqrtf(__fadd_rn(var, 1e-5f));
    #pragma unroll
    for (int i=0;i<24;i++){
        int j = threadIdx.x + 256*i;
        float n = __fdiv_rn(__fsub_rn(v[i],mu), sd);
        float a = __fadd_rn(__fmul_rn(n, w[j]), bia[j]);
        v[i] = fmaxf(a, 0.f);
    }
    // k-th largest over non-negative floats: bitwise radix select (uint order == float order).
    // Selection is order-based -> invariant to mu/sd bits (LN is monotone per row).
    unsigned prefix = 0u;
    for (int bit=30; bit>=0; --bit){
        unsigned cand = prefix | (1u<<bit);
        float cnt = 0.f;
        #pragma unroll
        for (int i=0;i<24;i++)
            cnt += (__float_as_uint(v[i]) >= cand) ? 1.f : 0.f;
        cnt = blockSum256(cnt, shf);
        if (cnt >= (float)KWTA_K) prefix = cand;
    }
    float thr = __uint_as_float(prefix);
    int b = r / TT, t = r % TT;
    #pragma unroll
    for (int i=0;i<24;i++){
        int j = threadIdx.x + 256*i;
        float o = (v[i] >= thr) ? v[i] : 0.f;
        if (TRANSV){
            int h = j >> 9, n = j & (HS-1);
            out[(((long)(b*NHH + h)*TT) + t)*HS + n] = o;
        } else {
            out[(long)r*HD + j] = o;
        }
    }
}

// ---------------- rope apply: (b,t,h,n) flat -> (b,h,t,n), no FMA contraction ---
__global__ void rope_apply_kernel(const float* __restrict__ qf, float* __restrict__ qr,
                                  const float2* __restrict__ tab){
    long i = (long)blockIdx.x*256 + threadIdx.x;    // pair index
    const long TOT = (long)BB*TT*NHH*(HS/2);
    if (i >= TOT) return;
    long pi = i*2;
    int n = (int)(pi % HS); long tmp = pi / HS;
    int h = (int)(tmp % NHH); tmp /= NHH;
    int t = (int)(tmp % TT);  int b = (int)(tmp / TT);
    float v0 = qf[pi], v1 = qf[pi+1];
    float2 cs = tab[t*(HS/2) + (n>>1)];
    float o0 = __fsub_rn(__fmul_rn(v0,cs.x), __fmul_rn(v1,cs.y));
    float o1 = __fadd_rn(__fmul_rn(v1,cs.x), __fmul_rn(v0,cs.y));
    long o = (((long)(b*NHH + h)*TT) + t)*HS + n;
    qr[o]   = o0;
    qr[o+1] = o1;
}

// ---------------- causal softmax (division semantics, CR expf proxy) ------------
__global__ __launch_bounds__(256)
void softmax_kernel(float* __restrict__ S){
    __shared__ float sv[TT];
    __shared__ float shf[32];
    __shared__ double shd[32];
    long row = blockIdx.x;               // (b*NH+h)*T + t
    int t = (int)(row % TT);
    float* p = S + row*(long)TT;
    for (int s=threadIdx.x; s<=t; s+=256) sv[s] = __fdiv_rn(p[s], SQRTN_F);
    __syncthreads();
    float mx = -CUDART_INF_F;
    for (int s=threadIdx.x; s<=t; s+=256) mx = fmaxf(mx, sv[s]);
    mx = blockMax256(mx, shf);
    double sum = 0.0;
    for (int s=threadIdx.x; s<=t; s+=256){
        float e = (float)exp((double)__fsub_rn(sv[s], mx));   // CR f32 exp proxy
        sv[s] = e; sum += (double)e;
    }
    sum = blockSumD256(sum, shd);
    float sumf = (float)sum;
    for (int s=threadIdx.x; s<TT; s+=256)
        p[s] = (s<=t) ? __fdiv_rn(sv[s], sumf) : 0.f;
}

// ---------------- (b,h,t,n) -> (b,t, h*N+n) ----------------
__global__ void yt_to_y_kernel(const float* __restrict__ yt, float* __restrict__ y){
    long i = (long)blockIdx.x*256 + threadIdx.x;
    const long TOT = (long)BB*NHH*TT*HS;
    if (i >= TOT) return;
    int n = (int)(i % HS); long tmp = i / HS;
    int t = (int)(tmp % TT); tmp /= TT;
    int h = (int)(tmp % NHH); int b = (int)(tmp / NHH);
    y[((long)(b*TT + t))*HD + h*HS + n] = yt[i];
}

// ---------------- decoder bias + output LN + residual (in-place x) ----------------
__global__ void dec_ln_res_kernel(const float* __restrict__ dec, const float* __restrict__ bias,
                                  const float* __restrict__ w, const float* __restrict__ b,
                                  float* __restrict__ x){
    __shared__ double shd[32];
    int r = blockIdx.x;
    const float* row = dec + (long)r*DD;
    float v[3]; double sum=0.0;
    #pragma unroll
    for (int i=0;i<3;i++){ int j=threadIdx.x+256*i; v[i]=__fadd_rn(row[j],bias[j]); sum+=(double)v[i]; }
    sum = blockSumD256(sum, shd);
    float mu = __fdiv_rn((float)sum, (float)DD);
    double sq=0.0;
    #pragma unroll
    for (int i=0;i<3;i++){ float d=__fsub_rn(v[i],mu); sq+=(double)__fmul_rn(d,d); }
    sq = blockSumD256(sq, shd);
    float var = __fdiv_rn((float)sq, (float)DD);
    float sd  = sqrtf(__fadd_rn(var, 1e-5f));
    #pragma unroll
    for (int i=0;i<3;i++){
        int j=threadIdx.x+256*i;
        long o = (long)r*DD+j;
        float n = __fdiv_rn(__fsub_rn(v[i],mu), sd);
        float ln = __fadd_rn(__fmul_rn(n, w[j]), b[j]);
        x[o] = __fadd_rn(x[o], ln);
    }
}

// ---------------- generic 128x128x8 SGEMM, Eigen-gebp panel accumulation --------
// Per output element: f32 FMA chain sequential within each KC-deep panel; panel
// subtotals added to the running f32 total in panel order — replicating Eigen's
// gebp "accumulate C per kc panel" bit behavior.
template<bool TRANSB, bool CAUSAL>
__global__ __launch_bounds__(256)
void sgemm_kernel(const float* __restrict__ A, const float* __restrict__ B, float* __restrict__ C,
                  int M, int N, int K, int lda, int ldb, int ldc,
                  long sA, long sB, long sC){
    int bz = blockIdx.z;
    A += (long)bz*sA; B += (long)bz*sB; C += (long)bz*sC;
    int cm = blockIdx.y, cn = blockIdx.x;
    if (CAUSAL && cn > cm) return;       // tile entirely above the causal diagonal
    __shared__ float As[8][128];
    __shared__ float Bs[8][128];
    int tid = threadIdx.x;
    int tc = tid & 15, tr = tid >> 4;    // 16x16 threads, 8x8 microtile each
    float tot[8][8], acc[8][8];
    #pragma unroll
    for (int i=0;i<8;i++)
        #pragma unroll
        for (int j=0;j<8;j++){ tot[i][j]=0.f; acc[i][j]=0.f; }

    int arow = tid >> 1;
    int acol = (tid & 1) * 4;
    const float* Aptr = A + ((long)(cm*128 + arow))*lda + acol;

    const float* Bptr;
    int brow=0, bcol=0;
    if (!TRANSB){
        brow = tid >> 5;                 // k (0..7)
        bcol = (tid & 31) * 4;           // n (0..124)
        Bptr = B + (long)brow*ldb + cn*128 + bcol;
    } else {
        brow = tid >> 1;                 // n (0..127)
        bcol = (tid & 1) * 4;            // k
        Bptr = B + ((long)(cn*128 + brow))*ldb + bcol;
    }

    for (int k0=0; k0<K; k0+=8){
        float4 a4 = *(const float4*)Aptr; Aptr += 8;
        As[acol+0][arow]=a4.x; As[acol+1][arow]=a4.y; As[acol+2][arow]=a4.z; As[acol+3][arow]=a4.w;
        if (!TRANSB){
            float4 b4 = *(const float4*)Bptr; Bptr += (long)8*ldb;
            *(float4*)&Bs[brow][bcol] = b4;
        } else {
            float4 b4 = *(const float4*)Bptr; Bptr += 8;
            Bs[bcol+0][brow]=b4.x; Bs[bcol+1][brow]=b4.y; Bs[bcol+2][brow]=b4.z; Bs[bcol+3][brow]=b4.w;
        }
        __syncthreads();
        #pragma unroll
        for (int kk=0;kk<8;kk++){
            float ra[8], rb[8];
            #pragma unroll
            for (int i=0;i<8;i++) ra[i]=As[kk][tr*8+i];
            #pragma unroll
            for (int j=0;j<8;j++) rb[j]=Bs[kk][tc*8+j];
            #pragma unroll
            for (int i=0;i<8;i++)
                #pragma unroll
                for (int j=0;j<8;j++) acc[i][j] = fmaf(ra[i], rb[j], acc[i][j]);
        }
        __syncthreads();
        // panel boundary: fold register panel subtotal into f32 running total
        int knext = k0 + 8;
        if ((knext % KC) == 0 || knext >= K){
            #pragma unroll
            for (int i=0;i<8;i++)
                #pragma unroll
                for (int j=0;j<8;j++){
                    tot[i][j] = __fadd_rn(tot[i][j], acc[i][j]);
                    acc[i][j] = 0.f;
                }
        }
    }
    #pragma unroll
    for (int i=0;i<8;i++){
        float* crow = C + ((long)(cm*128 + tr*8 + i))*ldc + cn*128 + tc*8;
        #pragma unroll
        for (int j=0;j<8;j++) crow[j] = tot[i][j];
    }
}

// ---------------- host ----------------
static void sgemm(const float* A, const float* B, float* C,
                  int M, int N, int K, int lda, int ldb, int ldc,
                  long sA, long sB, long sC, int batch, bool transb, bool causal){
    dim3 g(N/128, M/128, batch), blk(256,1,1);
    if (transb){
        if (causal) sgemm_kernel<true ,true ><<<g,blk>>>(A,B,C,M,N,K,lda,ldb,ldc,sA,sB,sC);
        else        sgemm_kernel<true ,false><<<g,blk>>>(A,B,C,M,N,K,lda,ldb,ldc,sA,sB,sC);
    } else {
        sgemm_kernel<false,false><<<g,blk>>>(A,B,C,M,N,K,lda,ldb,ldc,sA,sB,sC);
    }
}

extern "C" void kernel_launch(void* const* d_in, const int* in_sizes, int n_in,
                              void* d_out, int out_size){
    (void)in_sizes; (void)n_in; (void)out_size;
    const int*   idx       = (const int*)  d_in[0];
    const float* embed_w   = (const float*)d_in[1];
    const float* ln_in_w   = (const float*)d_in[2];
    const float* ln_in_b   = (const float*)d_in[3];
    const float* encoder   = (const float*)d_in[4];
    const float* encoder_v = (const float*)d_in[5];
    const float* lnq_w     = (const float*)d_in[6];
    const float* lnq_b     = (const float*)d_in[7];
    const float* lnv_w     = (const float*)d_in[8];
    const float* lnv_b     = (const float*)d_in[9];
    const float* decoder_w = (const float*)d_in[10];
    const float* decoder_b = (const float*)d_in[11];
    const float* ln_out_w  = (const float*)d_in[12];
    const float* ln_out_b  = (const float*)d_in[13];
    const float* lm_head_w = (const float*)d_in[14];
    float* out = (float*)d_out;

    float *x,*wenc,*wencv,*pre,*pre2,*qflat,*qr,*v,*S,*yt,*y,*dec; float2* rtab;
    cudaGetSymbolAddress((void**)&x,     g_x);
    cudaGetSymbolAddress((void**)&wenc,  g_wenc);
    cudaGetSymbolAddress((void**)&wencv, g_wencv);
    cudaGetSymbolAddress((void**)&pre,   g_pre);
    cudaGetSymbolAddress((void**)&pre2,  g_pre2);
    cudaGetSymbolAddress((void**)&qflat, g_qflat);
    cudaGetSymbolAddress((void**)&qr,    g_qr);
    cudaGetSymbolAddress((void**)&v,     g_v);
    cudaGetSymbolAddress((void**)&S,     g_S);
    cudaGetSymbolAddress((void**)&yt,    g_yt);
    cudaGetSymbolAddress((void**)&y,     g_y);
    cudaGetSymbolAddress((void**)&dec,   g_dec);
    cudaGetSymbolAddress((void**)&rtab,  g_rope);

    // one-time-per-launch prep (graph-captured, deterministic)
    {
        long n = (long)DD*HD;
        int blocks = (int)((n + 255)/256);
        repack_enc_kernel<<<blocks,256>>>(encoder,   wenc);
        repack_enc_kernel<<<blocks,256>>>(encoder_v, wencv);
        rope_table_kernel<<<(TT*(HS/2)+255)/256,256>>>(rtab);
    }
    embed_ln_kernel<<<ROWS,256>>>(idx, embed_w, ln_in_w, ln_in_b, x);

    const long bh = (long)BB*NHH;
    for (int l=0; l<LL; ++l){
        // q/v pre-activations
        sgemm(x, wenc,  pre,  ROWS, HD, DD, DD, HD, HD, 0,0,0, 1, false, false);
        sgemm(x, wencv, pre2, ROWS, HD, DD, DD, HD, HD, 0,0,0, 1, false, false);
        // LN + relu + kWTA
        ln_relu_kwta_kernel<false><<<ROWS,256>>>(pre,  lnq_w + (long)l*HD, lnq_b + (long)l*HD, qflat);
        ln_relu_kwta_kernel<true ><<<ROWS,256>>>(pre2, lnv_w + (long)l*HD, lnv_b + (long)l*HD, v);
        // rope (q used as both Q and K)
        {
            long pairs = (long)BB*TT*NHH*(HS/2);
            rope_apply_kernel<<<(int)((pairs+255)/256),256>>>(qflat, qr, rtab);
        }
        // S = qr @ qr^T per (b,h), causal tiles only
        sgemm(qr, qr, S, TT, TT, HS, HS, HS, TT,
              (long)TT*HS, (long)TT*HS, (long)TT*TT, (int)bh, true, true);
        softmax_kernel<<<(int)(bh*TT),256>>>(S);
        // Y = P @ V per (b,h)
        sgemm(S, v, yt, TT, HS, TT, TT, HS, HS,
              (long)TT*TT, (long)TT*HS, (long)TT*HS, (int)bh, false, false);
        {
            long n = (long)BB*NHH*TT*HS;
            yt_to_y_kernel<<<(int)((n+255)/256),256>>>(yt, y);
        }
        // decoder + LN + residual
        sgemm(y, decoder_w, dec, ROWS, DD, HD, HD, DD, DD, 0,0,0, 1, false, false);
        dec_ln_res_kernel<<<ROWS,256>>>(dec, decoder_b, ln_out_w, ln_out_b, x);
    }
    // logits = x @ lm_head^T
    sgemm(x, lm_head_w, out, ROWS, VOC, DD, DD, DD, VOC, 0,0,0, 1, true, false);
}

// round 17
// speedup vs baseline: 1.7276x; 1.7276x over previous
#include <cuda_runtime.h>
#include <math.h>
#include <math_constants.h>

#define BB   2
#define TT   1024
#define DD   768
#define NHH  12
#define HS   512
#define HD   6144
#define LL   4
#define VOC  32000
#define ROWS (BB*TT)
#define KWTA_K 921   // int(6144*0.15)

// Eigen gebp panel depth (multithreaded heuristic: min((l1-ksub)/kdiv, 320) -> 320 cap)
#define KC 320

// ---------------- scratch (device globals: no allocation allowed) ----------------
__device__ float g_x[ROWS*DD];
__device__ float g_wenc[DD*HD];
__device__ float g_wencv[DD*HD];
__device__ float g_pre[ROWS*HD];
__device__ float g_pre2[ROWS*HD];
__device__ float g_qflat[ROWS*HD];
__device__ float g_qr[(long)BB*NHH*TT*HS];
__device__ float g_v [(long)BB*NHH*TT*HS];
__device__ float g_S [(long)BB*NHH*TT*TT];
__device__ float g_yt[(long)BB*NHH*TT*HS];
__device__ float g_y [ROWS*HD];
__device__ float g_dec[ROWS*DD];
__device__ float2 g_rope[TT*(HS/2)];

// f32 constant equal to fl32(2.0*math.pi)
#define TWO_PI_F ((float)6.2831853071795864769252867665590)
// f32 constant equal to fl32(math.sqrt(512.0))
#define SQRTN_F  ((float)22.6274169979695207808)

// ---------------- reductions ----------------
__device__ __forceinline__ float warpSum(float v){
    #pragma unroll
    for (int o=16;o;o>>=1) v += __shfl_xor_sync(0xffffffffu, v, o);
    return v;
}
__device__ __forceinline__ double warpSumD(double v){
    #pragma unroll
    for (int o=16;o;o>>=1) v += __shfl_xor_sync(0xffffffffu, v, o);
    return v;
}
__device__ __forceinline__ float warpMax(float v){
    #pragma unroll
    for (int o=16;o;o>>=1) v = fmaxf(v, __shfl_xor_sync(0xffffffffu, v, o));
    return v;
}
__device__ __forceinline__ float blockSum256(float v, float* sh){
    v = warpSum(v);
    if ((threadIdx.x & 31)==0) sh[threadIdx.x>>5] = v;
    __syncthreads();
    float r = (threadIdx.x < 8) ? sh[threadIdx.x] : 0.f;
    if ((threadIdx.x>>5)==0){ r = warpSum(r); if (threadIdx.x==0) sh[0]=r; }
    __syncthreads();
    r = sh[0];
    __syncthreads();
    return r;
}
__device__ __forceinline__ double blockSumD256(double v, double* sh){
    v = warpSumD(v);
    if ((threadIdx.x & 31)==0) sh[threadIdx.x>>5] = v;
    __syncthreads();
    double r = (threadIdx.x < 8) ? sh[threadIdx.x] : 0.0;
    if ((threadIdx.x>>5)==0){ r = warpSumD(r); if (threadIdx.x==0) sh[0]=r; }
    __syncthreads();
    r = sh[0];
    __syncthreads();
    return r;
}
__device__ __forceinline__ float blockMax256(float v, float* sh){
    v = warpMax(v);
    if ((threadIdx.x & 31)==0) sh[threadIdx.x>>5] = v;
    __syncthreads();
    float r = (threadIdx.x < 8) ? sh[threadIdx.x] : -CUDART_INF_F;
    if ((threadIdx.x>>5)==0){ r = warpMax(r); if (threadIdx.x==0) sh[0]=r; }
    __syncthreads();
    r = sh[0];
    __syncthreads();
    return r;
}

// ---------------- embed + input layernorm (two-pass, division semantics) --------
__global__ void embed_ln_kernel(const int* __restrict__ idx, const float* __restrict__ emb,
                                const float* __restrict__ w, const float* __restrict__ b,
                                float* __restrict__ x){
    __shared__ double shd[32];
    int r = blockIdx.x;
    const float* row = emb + (long)idx[r]*DD;
    float v[3]; double sum=0.0;
    #pragma unroll
    for (int i=0;i<3;i++){ v[i]=row[threadIdx.x + 256*i]; sum+=(double)v[i]; }
    sum = blockSumD256(sum, shd);
    float mu = __fdiv_rn((float)sum, (float)DD);
    double sq=0.0;
    #pragma unroll
    for (int i=0;i<3;i++){ float d=__fsub_rn(v[i],mu); sq+=(double)__fmul_rn(d,d); }
    sq = blockSumD256(sq, shd);
    float var = __fdiv_rn((float)sq, (float)DD);
    float sd  = sqrtf(__fadd_rn(var, 1e-5f));
    #pragma unroll
    for (int i=0;i<3;i++){
        int j=threadIdx.x+256*i;
        float n = __fdiv_rn(__fsub_rn(v[i],mu), sd);
        x[(long)r*DD+j] = __fadd_rn(__fmul_rn(n, w[j]), b[j]);
    }
}

// ---------------- repack encoder (NH,D,N) -> (D, NH*N) ----------------
__global__ void repack_enc_kernel(const float* __restrict__ enc, float* __restrict__ w){
    long i = (long)blockIdx.x*256 + threadIdx.x;   // over D*HD
    if (i >= (long)DD*HD) return;
    int n = (int)(i % HS); long r = i / HS;
    int h = (int)(r % NHH); int d = (int)(r / NHH);
    w[i] = enc[((long)h*DD + d)*HS + n];
}

// ---------------- rope table: correctly-rounded f32 chain (glibc/AOR proxy) -----
__global__ void rope_table_kernel(float2* __restrict__ tab){
    int i = blockIdx.x*256 + threadIdx.x;           // t*(HS/2) + p
    if (i >= TT*(HS/2)) return;
    int p = i % (HS/2); int t = i / (HS/2);
    float e_f = __fdiv_rn((float)(2*p), 512.0f);    // exact (denominator 2^9)
    float pw  = (float)pow(10000.0, (double)e_f);   // CR f32 pow proxy
    float f1  = __fdiv_rn(1.0f, pw);
    float freq= __fdiv_rn(f1, TWO_PI_F);
    float ph  = __fmul_rn((float)t, freq);
    float frac= ph - floorf(ph);                    // exact for ph >= 0
    float ang = __fmul_rn(frac, TWO_PI_F);
    float c = (float)cos((double)ang);              // CR f32 cos proxy
    float s = (float)sin((double)ang);              // CR f32 sin proxy
    tab[i] = make_float2(c, s);
}

// ---------------- LN + relu + kWTA (two-pass LN, radix-select threshold) --------
template<bool TRANSV>
__global__ __launch_bounds__(256)
void ln_relu_kwta_kernel(const float* __restrict__ pre,
                         const float* __restrict__ w, const float* __restrict__ bia,
                         float* __restrict__ out){
    __shared__ double shd[32];
    __shared__ float shf[32];
    int r = blockIdx.x;                 // b*T + t
    const float* row = pre + (long)r*HD;
    float v[24];
    double sum = 0.0;
    #pragma unroll
    for (int i=0;i<24;i++){ v[i]=row[threadIdx.x + 256*i]; sum+=(double)v[i]; }
    sum = blockSumD256(sum, shd);
    float mu = __fdiv_rn((float)sum, (float)HD);
    double sq = 0.0;
    #pragma unroll
    for (int i=0;i<24;i++){ float d=__fsub_rn(v[i],mu); sq+=(double)__fmul_rn(d,d); }
    sq = blockSumD256(sq, shd);
    float var = __fdiv_rn((float)sq, (float)HD);
    float sd  = sqrtf(__fadd_rn(var, 1e-5f));
    #pragma unroll
    for (int i=0;i<24;i++){
        int j = threadIdx.x + 256*i;
        float n = __fdiv_rn(__fsub_rn(v[i],mu), sd);
        float a = __fadd_rn(__fmul_rn(n, w[j]), bia[j]);
        v[i] = fmaxf(a, 0.f);
    }
    // k-th largest over non-negative floats: bitwise radix select (uint order == float order)
    unsigned prefix = 0u;
    for (int bit=30; bit>=0; --bit){
        unsigned cand = prefix | (1u<<bit);
        float cnt = 0.f;
        #pragma unroll
        for (int i=0;i<24;i++)
            cnt += (__float_as_uint(v[i]) >= cand) ? 1.f : 0.f;
        cnt = blockSum256(cnt, shf);
        if (cnt >= (float)KWTA_K) prefix = cand;
    }
    float thr = __uint_as_float(prefix);
    int b = r / TT, t = r % TT;
    #pragma unroll
    for (int i=0;i<24;i++){
        int j = threadIdx.x + 256*i;
        float o = (v[i] >= thr) ? v[i] : 0.f;
        if (TRANSV){
            int h = j >> 9, n = j & (HS-1);
            out[(((long)(b*NHH + h)*TT) + t)*HS + n] = o;
        } else {
            out[(long)r*HD + j] = o;
        }
    }
}

// ---------------- rope apply: (b,t,h,n) flat -> (b,h,t,n), no FMA contraction ---
__global__ void rope_apply_kernel(const float* __restrict__ qf, float* __restrict__ qr,
                                  const float2* __restrict__ tab){
    long i = (long)blockIdx.x*256 + threadIdx.x;    // pair index
    const long TOT = (long)BB*TT*NHH*(HS/2);
    if (i >= TOT) return;
    long pi = i*2;
    int n = (int)(pi % HS); long tmp = pi / HS;
    int h = (int)(tmp % NHH); tmp /= NHH;
    int t = (int)(tmp % TT);  int b = (int)(tmp / TT);
    float v0 = qf[pi], v1 = qf[pi+1];
    float2 cs = tab[t*(HS/2) + (n>>1)];
    float o0 = __fsub_rn(__fmul_rn(v0,cs.x), __fmul_rn(v1,cs.y));
    float o1 = __fadd_rn(__fmul_rn(v1,cs.x), __fmul_rn(v0,cs.y));
    long o = (((long)(b*NHH + h)*TT) + t)*HS + n;
    qr[o]   = o0;
    qr[o+1] = o1;
}

// ---------------- causal softmax (division semantics, CR expf proxy) ------------
__global__ __launch_bounds__(256)
void softmax_kernel(float* __restrict__ S){
    __shared__ float sv[TT];
    __shared__ float shf[32];
    __shared__ double shd[32];
    long row = blockIdx.x;               // (b*NH+h)*T + t
    int t = (int)(row % TT);
    float* p = S + row*(long)TT;
    for (int s=threadIdx.x; s<=t; s+=256) sv[s] = __fdiv_rn(p[s], SQRTN_F);
    __syncthreads();
    float mx = -CUDART_INF_F;
    for (int s=threadIdx.x; s<=t; s+=256) mx = fmaxf(mx, sv[s]);
    mx = blockMax256(mx, shf);
    double sum = 0.0;
    for (int s=threadIdx.x; s<=t; s+=256){
        float e = (float)exp((double)__fsub_rn(sv[s], mx));   // CR f32 exp proxy
        sv[s] = e; sum += (double)e;
    }
    sum = blockSumD256(sum, shd);
    float sumf = (float)sum;
    for (int s=threadIdx.x; s<TT; s+=256)
        p[s] = (s<=t) ? __fdiv_rn(sv[s], sumf) : 0.f;
}

// ---------------- (b,h,t,n) -> (b,t, h*N+n) ----------------
__global__ void yt_to_y_kernel(const float* __restrict__ yt, float* __restrict__ y){
    long i = (long)blockIdx.x*256 + threadIdx.x;
    const long TOT = (long)BB*NHH*TT*HS;
    if (i >= TOT) return;
    int n = (int)(i % HS); long tmp = i / HS;
    int t = (int)(tmp % TT); tmp /= TT;
    int h = (int)(tmp % NHH); int b = (int)(tmp / NHH);
    y[((long)(b*TT + t))*HD + h*HS + n] = yt[i];
}

// ---------------- decoder bias + output LN + residual (in-place x) ----------------
__global__ void dec_ln_res_kernel(const float* __restrict__ dec, const float* __restrict__ bias,
                                  const float* __restrict__ w, const float* __restrict__ b,
                                  float* __restrict__ x){
    __shared__ double shd[32];
    int r = blockIdx.x;
    const float* row = dec + (long)r*DD;
    float v[3]; double sum=0.0;
    #pragma unroll
    for (int i=0;i<3;i++){ int j=threadIdx.x+256*i; v[i]=__fadd_rn(row[j],bias[j]); sum+=(double)v[i]; }
    sum = blockSumD256(sum, shd);
    float mu = __fdiv_rn((float)sum, (float)DD);
    double sq=0.0;
    #pragma unroll
    for (int i=0;i<3;i++){ float d=__fsub_rn(v[i],mu); sq+=(double)__fmul_rn(d,d); }
    sq = blockSumD256(sq, shd);
    float var = __fdiv_rn((float)sq, (float)DD);
    float sd  = sqrtf(__fadd_rn(var, 1e-5f));
    #pragma unroll
    for (int i=0;i<3;i++){
        int j=threadIdx.x+256*i;
        long o = (long)r*DD+j;
        float n = __fdiv_rn(__fsub_rn(v[i],mu), sd);
        float ln = __fadd_rn(__fmul_rn(n, w[j]), b[j]);
        x[o] = __fadd_rn(x[o], ln);
    }
}

// ---------------- 128x128x8 SGEMM, Eigen-gebp panel accumulation -----------------
// v2: double-buffered smem with register-staged prefetch (1 sync/k-step) and the
// panel running total kept in C (gmem RMW at panel boundaries). Per output
// element the fp32 op sequence is IDENTICAL to R15: sequential-k fmaf within a
// KC panel, panel subtotals folded in order with __fadd_rn.
template<bool TRANSB, bool CAUSAL>
__global__ __launch_bounds__(256,2)
void sgemm_kernel(const float* __restrict__ A, const float* __restrict__ B, float* __restrict__ C,
                  int M, int N, int K, int lda, int ldb, int ldc,
                  long sA, long sB, long sC){
    int bz = blockIdx.z;
    A += (long)bz*sA; B += (long)bz*sB; C += (long)bz*sC;
    int cm = blockIdx.y, cn = blockIdx.x;
    if (CAUSAL && cn > cm) return;       // tile entirely above the causal diagonal
    __shared__ float As[2][8][128];
    __shared__ float Bs[2][8][128];
    int tid = threadIdx.x;
    int tc = tid & 15, tr = tid >> 4;    // 16x16 threads, 8x8 microtile each
    float acc[8][8];
    #pragma unroll
    for (int i=0;i<8;i++)
        #pragma unroll
        for (int j=0;j<8;j++) acc[i][j]=0.f;

    int arow = tid >> 1;
    int acol = (tid & 1) * 4;
    const float* Aptr = A + ((long)(cm*128 + arow))*lda + acol;

    const float* Bptr;
    int brow=0, bcol=0;
    if (!TRANSB){
        brow = tid >> 5;                 // k (0..7)
        bcol = (tid & 31) * 4;           // n (0..124)
        Bptr = B + (long)brow*ldb + cn*128 + bcol;
    } else {
        brow = tid >> 1;                 // n (0..127)
        bcol = (tid & 1) * 4;            // k
        Bptr = B + ((long)(cn*128 + brow))*ldb + bcol;
    }

    // prologue: fill buffer 0
    {
        float4 a4 = *(const float4*)Aptr;
        As[0][acol+0][arow]=a4.x; As[0][acol+1][arow]=a4.y;
        As[0][acol+2][arow]=a4.z; As[0][acol+3][arow]=a4.w;
        float4 b4 = *(const float4*)Bptr;
        if (!TRANSB){
            *(float4*)&Bs[0][brow][bcol] = b4;
        } else {
            Bs[0][bcol+0][brow]=b4.x; Bs[0][bcol+1][brow]=b4.y;
            Bs[0][bcol+2][brow]=b4.z; Bs[0][bcol+3][brow]=b4.w;
        }
    }
    Aptr += 8;
    if (!TRANSB) Bptr += (long)8*ldb; else Bptr += 8;
    __syncthreads();

    float* Crow0 = C + ((long)(cm*128 + tr*8))*ldc + cn*128 + tc*8;
    int cur = 0;
    bool firstPanel = true;

    for (int k0=0; k0<K; k0+=8){
        bool hasNext = (k0+8 < K);
        float4 a4, b4;
        if (hasNext){
            a4 = *(const float4*)Aptr; Aptr += 8;
            b4 = *(const float4*)Bptr;
            if (!TRANSB) Bptr += (long)8*ldb; else Bptr += 8;
        }
        #pragma unroll
        for (int kk=0;kk<8;kk++){
            float4 ra0 = *(const float4*)&As[cur][kk][tr*8];
            float4 ra1 = *(const float4*)&As[cur][kk][tr*8+4];
            float4 rb0 = *(const float4*)&Bs[cur][kk][tc*8];
            float4 rb1 = *(const float4*)&Bs[cur][kk][tc*8+4];
            float ra[8] = {ra0.x,ra0.y,ra0.z,ra0.w, ra1.x,ra1.y,ra1.z,ra1.w};
            float rb[8] = {rb0.x,rb0.y,rb0.z,rb0.w, rb1.x,rb1.y,rb1.z,rb1.w};
            #pragma unroll
            for (int i=0;i<8;i++)
                #pragma unroll
                for (int j=0;j<8;j++) acc[i][j] = fmaf(ra[i], rb[j], acc[i][j]);
        }
        if (hasNext){
            int nxt = cur ^ 1;
            As[nxt][acol+0][arow]=a4.x; As[nxt][acol+1][arow]=a4.y;
            As[nxt][acol+2][arow]=a4.z; As[nxt][acol+3][arow]=a4.w;
            if (!TRANSB){
                *(float4*)&Bs[nxt][brow][bcol] = b4;
            } else {
                Bs[nxt][bcol+0][brow]=b4.x; Bs[nxt][bcol+1][brow]=b4.y;
                Bs[nxt][bcol+2][brow]=b4.z; Bs[nxt][bcol+3][brow]=b4.w;
            }
        }
        __syncthreads();

        // panel boundary: fold register panel subtotal into the f32 running total in C
        int knext = k0 + 8;
        if ((knext % KC) == 0 || knext >= K){
            if (firstPanel){
                #pragma unroll
                for (int i=0;i<8;i++){
                    float* crow = Crow0 + (long)i*ldc;
                    *(float4*)&crow[0] = make_float4(acc[i][0],acc[i][1],acc[i][2],acc[i][3]);
                    *(float4*)&crow[4] = make_float4(acc[i][4],acc[i][5],acc[i][6],acc[i][7]);
                    #pragma unroll
                    for (int j=0;j<8;j++) acc[i][j] = 0.f;
                }
                firstPanel = false;
            } else {
                #pragma unroll
                for (int i=0;i<8;i++){
                    float* crow = Crow0 + (long)i*ldc;
                    float4 c0 = *(const float4*)&crow[0];
                    float4 c1 = *(const float4*)&crow[4];
                    c0.x=__fadd_rn(c0.x,acc[i][0]); c0.y=__fadd_rn(c0.y,acc[i][1]);
                    c0.z=__fadd_rn(c0.z,acc[i][2]); c0.w=__fadd_rn(c0.w,acc[i][3]);
                    c1.x=__fadd_rn(c1.x,acc[i][4]); c1.y=__fadd_rn(c1.y,acc[i][5]);
                    c1.z=__fadd_rn(c1.z,acc[i][6]); c1.w=__fadd_rn(c1.w,acc[i][7]);
                    *(float4*)&crow[0] = c0;
                    *(float4*)&crow[4] = c1;
                    #pragma unroll
                    for (int j=0;j<8;j++) acc[i][j] = 0.f;
                }
            }
        }
        cur ^= 1;
    }
}

// ---------------- host ----------------
static void sgemm(const float* A, const float* B, float* C,
                  int M, int N, int K, int lda, int ldb, int ldc,
                  long sA, long sB, long sC, int batch, bool transb, bool causal){
    dim3 g(N/128, M/128, batch), blk(256,1,1);
    if (transb){
        if (causal) sgemm_kernel<true ,true ><<<g,blk>>>(A,B,C,M,N,K,lda,ldb,ldc,sA,sB,sC);
        else        sgemm_kernel<true ,false><<<g,blk>>>(A,B,C,M,N,K,lda,ldb,ldc,sA,sB,sC);
    } else {
        sgemm_kernel<false,false><<<g,blk>>>(A,B,C,M,N,K,lda,ldb,ldc,sA,sB,sC);
    }
}

extern "C" void kernel_launch(void* const* d_in, const int* in_sizes, int n_in,
                              void* d_out, int out_size){
    (void)in_sizes; (void)n_in; (void)out_size;
    const int*   idx       = (const int*)  d_in[0];
    const float* embed_w   = (const float*)d_in[1];
    const float* ln_in_w   = (const float*)d_in[2];
    const float* ln_in_b   = (const float*)d_in[3];
    const float* encoder   = (const float*)d_in[4];
    const float* encoder_v = (const float*)d_in[5];
    const float* lnq_w     = (const float*)d_in[6];
    const float* lnq_b     = (const float*)d_in[7];
    const float* lnv_w     = (const float*)d_in[8];
    const float* lnv_b     = (const float*)d_in[9];
    const float* decoder_w = (const float*)d_in[10];
    const float* decoder_b = (const float*)d_in[11];
    const float* ln_out_w  = (const float*)d_in[12];
    const float* ln_out_b  = (const float*)d_in[13];
    const float* lm_head_w = (const float*)d_in[14];
    float* out = (float*)d_out;

    float *x,*wenc,*wencv,*pre,*pre2,*qflat,*qr,*v,*S,*yt,*y,*dec; float2* rtab;
    cudaGetSymbolAddress((void**)&x,     g_x);
    cudaGetSymbolAddress((void**)&wenc,  g_wenc);
    cudaGetSymbolAddress((void**)&wencv, g_wencv);
    cudaGetSymbolAddress((void**)&pre,   g_pre);
    cudaGetSymbolAddress((void**)&pre2,  g_pre2);
    cudaGetSymbolAddress((void**)&qflat, g_qflat);
    cudaGetSymbolAddress((void**)&qr,    g_qr);
    cudaGetSymbolAddress((void**)&v,     g_v);
    cudaGetSymbolAddress((void**)&S,     g_S);
    cudaGetSymbolAddress((void**)&yt,    g_yt);
    cudaGetSymbolAddress((void**)&y,     g_y);
    cudaGetSymbolAddress((void**)&dec,   g_dec);
    cudaGetSymbolAddress((void**)&rtab,  g_rope);

    // one-time-per-launch prep (graph-captured, deterministic)
    {
        long n = (long)DD*HD;
        int blocks = (int)((n + 255)/256);
        repack_enc_kernel<<<blocks,256>>>(encoder,   wenc);
        repack_enc_kernel<<<blocks,256>>>(encoder_v, wencv);
        rope_table_kernel<<<(TT*(HS/2)+255)/256,256>>>(rtab);
    }
    embed_ln_kernel<<<ROWS,256>>>(idx, embed_w, ln_in_w, ln_in_b, x);

    const long bh = (long)BB*NHH;
    for (int l=0; l<LL; ++l){
        // q/v pre-activations
        sgemm(x, wenc,  pre,  ROWS, HD, DD, DD, HD, HD, 0,0,0, 1, false, false);
        sgemm(x, wencv, pre2, ROWS, HD, DD, DD, HD, HD, 0,0,0, 1, false, false);
        // LN + relu + kWTA
        ln_relu_kwta_kernel<false><<<ROWS,256>>>(pre,  lnq_w + (long)l*HD, lnq_b + (long)l*HD, qflat);
        ln_relu_kwta_kernel<true ><<<ROWS,256>>>(pre2, lnv_w + (long)l*HD, lnv_b + (long)l*HD, v);
        // rope (q used as both Q and K)
        {
            long pairs = (long)BB*TT*NHH*(HS/2);
            rope_apply_kernel<<<(int)((pairs+255)/256),256>>>(qflat, qr, rtab);
        }
        // S = qr @ qr^T per (b,h), causal tiles only
        sgemm(qr, qr, S, TT, TT, HS, HS, HS, TT,
              (long)TT*HS, (long)TT*HS, (long)TT*TT, (int)bh, true, true);
        softmax_kernel<<<(int)(bh*TT),256>>>(S);
        // Y = P @ V per (b,h)
        sgemm(S, v, yt, TT, HS, TT, TT, HS, HS,
              (long)TT*TT, (long)TT*HS, (long)TT*HS, (int)bh, false, false);
        {
            long n = (long)BB*NHH*TT*HS;
            yt_to_y_kernel<<<(int)((n+255)/256),256>>>(yt, y);
        }
        // decoder + LN + residual
        sgemm(y, decoder_w, dec, ROWS, DD, HD, HD, DD, DD, 0,0,0, 1, false, false);
        dec_ln_res_kernel<<<ROWS,256>>>(dec, decoder_b, ln_out_w, ln_out_b, x);
    }
    // logits = x @ lm_head^T
    sgemm(x, lm_head_w, out, ROWS, VOC, DD, DD, DD, VOC, 0,0,0, 1, true, false);
}